// round 12
// baseline (speedup 1.0000x reference)
#include <cuda_runtime.h>

// ---------------------------------------------------------------------------
// Problem constants
// ---------------------------------------------------------------------------
#define Bc    8
#define Ac    60000
#define Cc    150                 // 1 + (10+19+39+69+12)
#define Gc    20
#define Tc    5
#define BAc   (Bc * Ac)           // 480,000 anchors
#define NCONF (BAc * Cc)          // 72,000,000 floats
#define NV4   (NCONF / 4)         // 18,000,000 float4s
#define RW    8                   // padded words per bitmask row
#define NROWS (Bc * (Gc + 1))     // 168 rows
#define NBLK  1184                // 148 SMs * 8 blocks: single FULL wave

#define POSBIT 0x40000000u

#define C0w   (-0.75f * 0.69314718056f)  // -(1-alpha) * ln2  (label 0)
#define C1w   (-0.25f * 0.69314718056f)  // -alpha     * ln2  (label 1)

__device__ unsigned g_bits[NROWS * RW];
__device__ int4     g_info[BAc];   // {row|flags, C0*mask, C1*mask, 0}
__device__ double   g_acc[3];      // [0]=reg_sum, [1]=cls_sum, [2]=num_pos
__device__ unsigned g_done;        // completed-block ticket counter

// ---------------------------------------------------------------------------
// MUFU wrappers
// ---------------------------------------------------------------------------
__device__ __forceinline__ float mufu_tanh(float x) {
    float y; asm("tanh.approx.f32 %0, %1;" : "=f"(y) : "f"(x)); return y;
}
__device__ __forceinline__ float mufu_lg2(float x) {
    float y; asm("lg2.approx.f32 %0, %1;" : "=f"(y) : "f"(x)); return y;
}

// ---------------------------------------------------------------------------
// Focal via tanh (2 MUFU):
//   p = sigmoid(x) = 0.5 + 0.5*tanh(x/2)
//   P = l ? p : 1-p = 0.5 + (l ? +0.5 : -0.5)*t
//   term = A * (-ln P) * (1-P)^2 = coef * lg2(P) * (1-P)^2,  coef = -A*ln2*mask
// Label select feeds the FFMA *after* TANH -> overlapped with MUFU latency.
// Coefficients arrive pre-masked from g_info (no mask math in the loop).
// ---------------------------------------------------------------------------
__device__ __forceinline__ void focal(float x, bool l, float c0m, float c1m,
                                      float& acc) {
    float t    = mufu_tanh(0.5f * x);
    float sgn  = l ? 0.5f : -0.5f;
    float P    = fmaf(sgn, t, 0.5f);
    float lgP  = mufu_lg2(P);
    float w    = 1.0f - P;
    float coef = l ? c1m : c0m;
    acc = fmaf(coef * lgP, w * w, acc);
}

// ---------------------------------------------------------------------------
// Kernel 1 (prep): per-anchor info word + label bitmask table.
//   g_info[a] = {b*21+max(lb,0) | pos<<30,  C0w*mask,  C1w*mask,  0}
//   g_bits:  bit 0 = (lb>0);  bit 1+k = class-k present in group lb-1
// ---------------------------------------------------------------------------
__global__ void prep_kernel(const int* __restrict__ lbin,
                            const int* __restrict__ gt_labels) {
    int a = blockIdx.x * 256 + threadIdx.x;
    if (a < BAc) {
        int lb = lbin[a];
        int b  = a / Ac;
        unsigned enc = (unsigned)(b * (Gc + 1) + max(lb, 0));
        if (lb > 0) enc |= POSBIT;
        float m = (lb >= 0) ? 1.f : 0.f;
        g_info[a] = make_int4((int)enc,
                              __float_as_int(C0w * m),
                              __float_as_int(C1w * m), 0);
    }
    if (blockIdx.x == 0 && threadIdx.x < NROWS) {
        int b = threadIdx.x / (Gc + 1), g = threadIdx.x % (Gc + 1);
        unsigned w[RW] = {0u, 0u, 0u, 0u, 0u, 0u, 0u, 0u};
        if (g > 0) {
            w[0] = 1u;
            const int off[5] = {1, 11, 30, 69, 138};
            int grp = g - 1;
#pragma unroll
            for (int h = 0; h < 5; h++)
#pragma unroll
                for (int t = 0; t < Tc; t++) {
                    int v = __ldg(&gt_labels[((b * Gc + grp) * 5 + h) * Tc + t]);
                    if (v >= 0) {
                        int bit = off[h] + v;
                        w[bit >> 5] |= (1u << (bit & 31));
                    }
                }
        }
#pragma unroll
        for (int k = 0; k < RW; k++)
            g_bits[threadIdx.x * RW + k] = w[k];
    }
}

// ---------------------------------------------------------------------------
// Kernel 2 (main): fused cls/reg/npos + last-block finalize.
// ---------------------------------------------------------------------------
__global__ void __launch_bounds__(256, 8)
main_kernel(const float4* __restrict__ conf4,
            const float4* __restrict__ pred4,
            const float4* __restrict__ gt4,
            float*        __restrict__ out) {
    __shared__ unsigned sb[NROWS * RW];        // 5.25 KB
    for (int i = threadIdx.x; i < NROWS * RW; i += 256)
        sb[i] = g_bits[i];
    __syncthreads();

    const int tid    = blockIdx.x * 256 + threadIdx.x;
    const int stride = NBLK * 256;

    float cls0 = 0.f, cls1 = 0.f, cls2 = 0.f, cls3 = 0.f;

    // ---- classification over 18M float4s ----
#pragma unroll 2
    for (int i = tid; i < NV4; i += stride) {
        float4 v = __ldcs(&conf4[i]);           // streaming: no L2 reuse
        unsigned base = (unsigned)i << 2;
        unsigned a = base / (unsigned)Cc;       // magic-mul
        int c = (int)(base - a * Cc);           // even, 0..148
        int4 gi = __ldg(&g_info[a]);
        int row = gi.x & 0xFFFF;

        const unsigned* rp = &sb[(row << 3) + (c >> 5)];
        unsigned bits = __funnelshift_r(rp[0], rp[1], c);  // low 4 bits = labels
        float c0A = __int_as_float(gi.y), c1A = __int_as_float(gi.z);
        float c0B = c0A,                  c1B = c1A;

        if (c == 148) {                         // anchor crossing (2+2 split)
            int4 gi2 = __ldg(&g_info[a + 1]);
            int row2 = gi2.x & 0xFFFF;
            bits = (bits & 3u) | ((sb[row2 << 3] & 3u) << 2);
            c0B = __int_as_float(gi2.y); c1B = __int_as_float(gi2.z);
        }

        focal(v.x, (bits      & 1u) != 0u, c0A, c1A, cls0);
        focal(v.y, ((bits>>1) & 1u) != 0u, c0A, c1A, cls1);
        focal(v.z, ((bits>>2) & 1u) != 0u, c0B, c1B, cls2);
        focal(v.w, ((bits>>3) & 1u) != 0u, c0B, c1B, cls3);
    }

    // ---- regression + pos count over 480k anchors ----
    float reg = 0.f, npos = 0.f;
    for (int a1 = tid; a1 < BAc; a1 += stride) {
        int rv = __ldg(&g_info[a1].x);
        if (rv & (int)POSBIT) {
            npos += 1.0f;
            float4 p = pred4[a1];
            float4 g = gt4[a1];
            float d[4] = {p.x - g.x, p.y - g.y, p.z - g.z, p.w - g.w};
#pragma unroll
            for (int k = 0; k < 4; k++) {
                float n = fabsf(d[k]);
                reg += (n < (1.0f / 9.0f)) ? 4.5f * n * n : n - (1.0f / 18.0f);
            }
        }
    }

    // ---- block reduction ----
    float cls = (cls0 + cls1) + (cls2 + cls3);
#pragma unroll
    for (int o = 16; o > 0; o >>= 1) {
        cls  += __shfl_down_sync(0xFFFFFFFFu, cls,  o);
        reg  += __shfl_down_sync(0xFFFFFFFFu, reg,  o);
        npos += __shfl_down_sync(0xFFFFFFFFu, npos, o);
    }
    __shared__ float red[3][8];
    int warp = threadIdx.x >> 5, lane = threadIdx.x & 31;
    if (lane == 0) { red[0][warp] = reg; red[1][warp] = cls; red[2][warp] = npos; }
    __syncthreads();

    // ---- commit + last-block finalize (verified ticket pattern) ----
    if (threadIdx.x == 0) {
        float r0 = 0.f, r1 = 0.f, r2 = 0.f;
#pragma unroll
        for (int w = 0; w < 8; w++) { r0 += red[0][w]; r1 += red[1][w]; r2 += red[2][w]; }
        atomicAdd(&g_acc[0], (double)r0);
        atomicAdd(&g_acc[1], (double)r1);
        atomicAdd(&g_acc[2], (double)r2);
        __threadfence();
        unsigned ticket = atomicAdd(&g_done, 1u);
        if (ticket == NBLK - 1) {
            double a0 = __longlong_as_double(
                (long long)atomicExch((unsigned long long*)&g_acc[0], 0ull));
            double a1 = __longlong_as_double(
                (long long)atomicExch((unsigned long long*)&g_acc[1], 0ull));
            double a2 = __longlong_as_double(
                (long long)atomicExch((unsigned long long*)&g_acc[2], 0ull));
            atomicExch(&g_done, 0u);
            double np = (a2 < 1.0) ? 1.0 : a2;
            out[0] = (float)(a0 / (np * 4.0));
            out[1] = (float)(a1 / (np * 6.0));
        }
    }
}

extern "C" void kernel_launch(void* const* d_in, const int* in_sizes, int n_in,
                              void* d_out, int out_size) {
    const float* conf       = (const float*)d_in[0];   // (8, 60000, 150) f32
    const float* pred       = (const float*)d_in[1];   // (8, 60000, 4)   f32
    const float* gt_loc     = (const float*)d_in[2];   // (8, 60000, 4)   f32
    const int*   gt_labels  = (const int*)  d_in[3];   // (8, 20, 5, 5)   i32
    // d_in[4] = counts: not used by the computation
    const int*   labels_bin = (const int*)  d_in[5];   // (8, 60000)      i32
    float* out = (float*)d_out;

    prep_kernel<<<(BAc + 255) / 256, 256>>>(labels_bin, gt_labels);

    main_kernel<<<NBLK, 256>>>((const float4*)conf,
                               (const float4*)pred,
                               (const float4*)gt_loc,
                               out);
}

// round 13
// speedup vs baseline: 1.1666x; 1.1666x over previous
#include <cuda_runtime.h>

// ---------------------------------------------------------------------------
// Problem constants
// ---------------------------------------------------------------------------
#define Bc    8
#define Ac    60000
#define Cc    150                 // 1 + (10+19+39+69+12)
#define Gc    20
#define Tc    5
#define BAc   (Bc * Ac)           // 480,000 anchors
#define NCONF (BAc * Cc)          // 72,000,000 floats
#define NV4   (NCONF / 4)         // 18,000,000 float4s
#define NV8   (NV4 / 2)           // 9,000,000 float4-pairs
#define RW    8                   // padded words per bitmask row
#define NROWS (Bc * (Gc + 1))     // 168 rows
#define NBLK  888                 // 148 SMs * 6 blocks: single wave @ 40 regs

#define POSBIT 0x40000000u

#define C0w   (-0.75f * 0.69314718056f)  // -(1-alpha) * ln2  (label 0)
#define C1w   (-0.25f * 0.69314718056f)  // -alpha     * ln2  (label 1)

__device__ unsigned g_bits[NROWS * RW];
__device__ int      g_row[BAc];    // per-anchor: row | pos<<30 | neg-> sign bit
__device__ double   g_acc[3];      // [0]=reg_sum, [1]=cls_sum, [2]=num_pos
__device__ unsigned g_done;        // completed-block ticket counter

// ---------------------------------------------------------------------------
// MUFU wrappers
// ---------------------------------------------------------------------------
__device__ __forceinline__ float mufu_tanh(float x) {
    float y; asm("tanh.approx.f32 %0, %1;" : "=f"(y) : "f"(x)); return y;
}
__device__ __forceinline__ float mufu_lg2(float x) {
    float y; asm("lg2.approx.f32 %0, %1;" : "=f"(y) : "f"(x)); return y;
}

// ---------------------------------------------------------------------------
// Focal via tanh (2 MUFU):
//   P = 0.5 + (l ? +0.5 : -0.5) * tanh(x/2)    ( = l ? p : 1-p )
//   term = m * (l ? C1w : C0w) * lg2(P) * (1-P)^2
// Chain starts directly from x; label/mask ops trail the TANH (latency-hidden).
// ---------------------------------------------------------------------------
__device__ __forceinline__ void focal(float x, bool l, float m, float& acc) {
    float t    = mufu_tanh(0.5f * x);
    float sgn  = l ? 0.5f : -0.5f;
    float P    = fmaf(sgn, t, 0.5f);
    float lgP  = mufu_lg2(P);
    float w    = 1.0f - P;
    float coef = (l ? C1w : C0w) * m;
    acc = fmaf(coef * lgP, w * w, acc);
}

// ---------------------------------------------------------------------------
// Kernel 1 (prep): per-anchor routing word + label bitmask table.
//   g_row[a] = (b*21 + max(lb,0)) | (lb>0)<<30 | (lb<0)<<31
//   g_bits:  bit 0 = (lb>0);  bit 1+k = class-k present in group lb-1
// ---------------------------------------------------------------------------
__global__ void prep_kernel(const int* __restrict__ lbin,
                            const int* __restrict__ gt_labels) {
    int a = blockIdx.x * 256 + threadIdx.x;
    if (a < BAc) {
        int lb = lbin[a];
        int b  = a / Ac;
        unsigned enc = (unsigned)(b * (Gc + 1) + max(lb, 0));
        if (lb > 0) enc |= POSBIT;
        if (lb < 0) enc |= 0x80000000u;
        g_row[a] = (int)enc;
    }
    if (blockIdx.x == 0 && threadIdx.x < NROWS) {
        int b = threadIdx.x / (Gc + 1), g = threadIdx.x % (Gc + 1);
        unsigned w[RW] = {0u, 0u, 0u, 0u, 0u, 0u, 0u, 0u};
        if (g > 0) {
            w[0] = 1u;
            const int off[5] = {1, 11, 30, 69, 138};
            int grp = g - 1;
#pragma unroll
            for (int h = 0; h < 5; h++)
#pragma unroll
                for (int t = 0; t < Tc; t++) {
                    int v = __ldg(&gt_labels[((b * Gc + grp) * 5 + h) * Tc + t]);
                    if (v >= 0) {
                        int bit = off[h] + v;
                        w[bit >> 5] |= (1u << (bit & 31));
                    }
                }
        }
#pragma unroll
        for (int k = 0; k < RW; k++)
            g_bits[threadIdx.x * RW + k] = w[k];
    }
}

// ---------------------------------------------------------------------------
// Kernel 2 (main): 8 channels (2 float4s) per iteration; index work amortized.
// ---------------------------------------------------------------------------
__global__ void __launch_bounds__(256, 6)
main_kernel(const float4* __restrict__ conf4,
            const float4* __restrict__ pred4,
            const float4* __restrict__ gt4,
            float*        __restrict__ out) {
    __shared__ unsigned sb[NROWS * RW];        // 5.25 KB
    for (int i = threadIdx.x; i < NROWS * RW; i += 256)
        sb[i] = g_bits[i];
    __syncthreads();

    const int tid    = blockIdx.x * 256 + threadIdx.x;
    const int stride = NBLK * 256;

    float cls0 = 0.f, cls1 = 0.f, cls2 = 0.f, cls3 = 0.f;

    // ---- classification: 9M float4-pairs, 8 consecutive channels each ----
    for (int j = tid; j < NV8; j += stride) {
        float4 v0 = __ldcs(&conf4[2 * j]);
        float4 v1 = __ldcs(&conf4[2 * j + 1]);
        unsigned base = (unsigned)j << 3;          // 8 channels per iteration
        unsigned a = base / (unsigned)Cc;          // magic-mul
        int c = (int)(base - a * Cc);              // even, 0..148
        int rv = __ldg(&g_row[a]);
        int row = rv & 0xFFFF;

        const unsigned* rp = &sb[(row << 3) + (c >> 5)];
        unsigned bits = __funnelshift_r(rp[0], rp[1], c);  // low 8 bits = labels
        float m = (rv >= 0) ? 1.f : 0.f;
        // per lane-pair masks: (0,1)=A (2,3)=B (4,5)=C (6,7)=D
        float mA = m, mB = m, mC = m, mD = m;

        if (c >= 144) {                            // anchor crossing (rare)
            int n1 = Cc - c;                       // 6, 4, or 2 lanes in a
            int rv2 = __ldg(&g_row[a + 1]);
            int row2 = rv2 & 0xFFFF;
            unsigned bits2 = sb[row2 << 3];
            bits = (bits & ((1u << n1) - 1u)) | (bits2 << n1);
            float m2 = (rv2 >= 0) ? 1.f : 0.f;
            if (n1 <= 2) mB = m2;
            if (n1 <= 4) mC = m2;
            mD = m2;
        }

        focal(v0.x, (bits      & 1u) != 0u, mA, cls0);
        focal(v0.y, ((bits>>1) & 1u) != 0u, mA, cls1);
        focal(v0.z, ((bits>>2) & 1u) != 0u, mB, cls2);
        focal(v0.w, ((bits>>3) & 1u) != 0u, mB, cls3);
        focal(v1.x, ((bits>>4) & 1u) != 0u, mC, cls0);
        focal(v1.y, ((bits>>5) & 1u) != 0u, mC, cls1);
        focal(v1.z, ((bits>>6) & 1u) != 0u, mD, cls2);
        focal(v1.w, ((bits>>7) & 1u) != 0u, mD, cls3);
    }

    // ---- regression + pos count over 480k anchors ----
    float reg = 0.f, npos = 0.f;
    for (int a1 = tid; a1 < BAc; a1 += stride) {
        int rv = __ldg(&g_row[a1]);
        if (rv & (int)POSBIT) {
            npos += 1.0f;
            float4 p = pred4[a1];
            float4 g = gt4[a1];
            float d[4] = {p.x - g.x, p.y - g.y, p.z - g.z, p.w - g.w};
#pragma unroll
            for (int k = 0; k < 4; k++) {
                float n = fabsf(d[k]);
                reg += (n < (1.0f / 9.0f)) ? 4.5f * n * n : n - (1.0f / 18.0f);
            }
        }
    }

    // ---- block reduction ----
    float cls = (cls0 + cls1) + (cls2 + cls3);
#pragma unroll
    for (int o = 16; o > 0; o >>= 1) {
        cls  += __shfl_down_sync(0xFFFFFFFFu, cls,  o);
        reg  += __shfl_down_sync(0xFFFFFFFFu, reg,  o);
        npos += __shfl_down_sync(0xFFFFFFFFu, npos, o);
    }
    __shared__ float red[3][8];
    int warp = threadIdx.x >> 5, lane = threadIdx.x & 31;
    if (lane == 0) { red[0][warp] = reg; red[1][warp] = cls; red[2][warp] = npos; }
    __syncthreads();

    // ---- commit + last-block finalize (verified ticket pattern) ----
    if (threadIdx.x == 0) {
        float r0 = 0.f, r1 = 0.f, r2 = 0.f;
#pragma unroll
        for (int w = 0; w < 8; w++) { r0 += red[0][w]; r1 += red[1][w]; r2 += red[2][w]; }
        atomicAdd(&g_acc[0], (double)r0);
        atomicAdd(&g_acc[1], (double)r1);
        atomicAdd(&g_acc[2], (double)r2);
        __threadfence();
        unsigned ticket = atomicAdd(&g_done, 1u);
        if (ticket == NBLK - 1) {
            double a0 = __longlong_as_double(
                (long long)atomicExch((unsigned long long*)&g_acc[0], 0ull));
            double a1 = __longlong_as_double(
                (long long)atomicExch((unsigned long long*)&g_acc[1], 0ull));
            double a2 = __longlong_as_double(
                (long long)atomicExch((unsigned long long*)&g_acc[2], 0ull));
            atomicExch(&g_done, 0u);
            double np = (a2 < 1.0) ? 1.0 : a2;
            out[0] = (float)(a0 / (np * 4.0));
            out[1] = (float)(a1 / (np * 6.0));
        }
    }
}

extern "C" void kernel_launch(void* const* d_in, const int* in_sizes, int n_in,
                              void* d_out, int out_size) {
    const float* conf       = (const float*)d_in[0];   // (8, 60000, 150) f32
    const float* pred       = (const float*)d_in[1];   // (8, 60000, 4)   f32
    const float* gt_loc     = (const float*)d_in[2];   // (8, 60000, 4)   f32
    const int*   gt_labels  = (const int*)  d_in[3];   // (8, 20, 5, 5)   i32
    // d_in[4] = counts: not used by the computation
    const int*   labels_bin = (const int*)  d_in[5];   // (8, 60000)      i32
    float* out = (float*)d_out;

    prep_kernel<<<(BAc + 255) / 256, 256>>>(labels_bin, gt_labels);

    main_kernel<<<NBLK, 256>>>((const float4*)conf,
                               (const float4*)pred,
                               (const float4*)gt_loc,
                               out);
}

// round 14
// speedup vs baseline: 1.3490x; 1.1564x over previous
#include <cuda_runtime.h>

// ---------------------------------------------------------------------------
// Problem constants
// ---------------------------------------------------------------------------
#define Bc    8
#define Ac    60000
#define Cc    150                 // 1 + (10+19+39+69+12)
#define Gc    20
#define Tc    5
#define BAc   (Bc * Ac)           // 480,000 anchors
#define NCONF (BAc * Cc)          // 72,000,000 floats
#define NV16  (NCONF / 16)        // 4,500,000 16-channel groups
#define RW    8                   // padded words per bitmask row
#define NROWS (Bc * (Gc + 1))     // 168 rows
#define NBLK  740                 // 148 SMs * 5 blocks: single wave @ 48 regs

#define POSBIT 0x40000000u

#define C0w   (-0.75f * 0.69314718056f)  // -(1-alpha) * ln2  (label 0)
#define C1w   (-0.25f * 0.69314718056f)  // -alpha     * ln2  (label 1)

__device__ unsigned g_bits[NROWS * RW];
__device__ int      g_row[BAc];    // per-anchor: row | pos<<30 | neg->sign bit
__device__ double   g_acc[3];      // [0]=reg_sum, [1]=cls_sum, [2]=num_pos
__device__ unsigned g_done;        // completed-block ticket counter

// ---------------------------------------------------------------------------
// MUFU wrappers
// ---------------------------------------------------------------------------
__device__ __forceinline__ float mufu_tanh(float x) {
    float y; asm("tanh.approx.f32 %0, %1;" : "=f"(y) : "f"(x)); return y;
}
__device__ __forceinline__ float mufu_lg2(float x) {
    float y; asm("lg2.approx.f32 %0, %1;" : "=f"(y) : "f"(x)); return y;
}

// ---------------------------------------------------------------------------
// Focal via tanh (2 MUFU):
//   P = 0.5 + (l ? +0.5 : -0.5) * tanh(x/2)    ( = l ? p : 1-p )
//   term = m * (l ? C1w : C0w) * lg2(P) * (1-P)^2
// Chain starts directly from x; label/mask ops trail the TANH (latency-hidden).
// ---------------------------------------------------------------------------
__device__ __forceinline__ void focal(float x, bool l, float m, float& acc) {
    float t    = mufu_tanh(0.5f * x);
    float sgn  = l ? 0.5f : -0.5f;
    float P    = fmaf(sgn, t, 0.5f);
    float lgP  = mufu_lg2(P);
    float w    = 1.0f - P;
    float coef = (l ? C1w : C0w) * m;
    acc = fmaf(coef * lgP, w * w, acc);
}

// ---------------------------------------------------------------------------
// Kernel 1 (prep): per-anchor routing word + label bitmask table.
//   g_row[a] = (b*21 + max(lb,0)) | (lb>0)<<30 | (lb<0)<<31
//   g_bits:  bit 0 = (lb>0);  bit 1+k = class-k present in group lb-1
// ---------------------------------------------------------------------------
__global__ void prep_kernel(const int* __restrict__ lbin,
                            const int* __restrict__ gt_labels) {
    int a = blockIdx.x * 256 + threadIdx.x;
    if (a < BAc) {
        int lb = lbin[a];
        int b  = a / Ac;
        unsigned enc = (unsigned)(b * (Gc + 1) + max(lb, 0));
        if (lb > 0) enc |= POSBIT;
        if (lb < 0) enc |= 0x80000000u;
        g_row[a] = (int)enc;
    }
    if (blockIdx.x == 0 && threadIdx.x < NROWS) {
        int b = threadIdx.x / (Gc + 1), g = threadIdx.x % (Gc + 1);
        unsigned w[RW] = {0u, 0u, 0u, 0u, 0u, 0u, 0u, 0u};
        if (g > 0) {
            w[0] = 1u;
            const int off[5] = {1, 11, 30, 69, 138};
            int grp = g - 1;
#pragma unroll
            for (int h = 0; h < 5; h++)
#pragma unroll
                for (int t = 0; t < Tc; t++) {
                    int v = __ldg(&gt_labels[((b * Gc + grp) * 5 + h) * Tc + t]);
                    if (v >= 0) {
                        int bit = off[h] + v;
                        w[bit >> 5] |= (1u << (bit & 31));
                    }
                }
        }
#pragma unroll
        for (int k = 0; k < RW; k++)
            g_bits[threadIdx.x * RW + k] = w[k];
    }
}

// ---------------------------------------------------------------------------
// Kernel 2 (main): 16 channels (4 float4s) per iteration.
// ---------------------------------------------------------------------------
__global__ void __launch_bounds__(256, 5)
main_kernel(const float4* __restrict__ conf4,
            const float4* __restrict__ pred4,
            const float4* __restrict__ gt4,
            float*        __restrict__ out) {
    __shared__ unsigned sb[NROWS * RW];        // 5.25 KB
    for (int i = threadIdx.x; i < NROWS * RW; i += 256)
        sb[i] = g_bits[i];
    __syncthreads();

    const int tid    = blockIdx.x * 256 + threadIdx.x;
    const int stride = NBLK * 256;

    float cls0 = 0.f, cls1 = 0.f, cls2 = 0.f, cls3 = 0.f;

    // ---- classification: 4.5M groups of 16 consecutive channels ----
    for (int j = tid; j < NV16; j += stride) {
        float4 v0 = __ldcs(&conf4[4 * j]);
        float4 v1 = __ldcs(&conf4[4 * j + 1]);
        float4 v2 = __ldcs(&conf4[4 * j + 2]);
        float4 v3 = __ldcs(&conf4[4 * j + 3]);
        unsigned base = (unsigned)j << 4;          // 16 channels per group
        unsigned a = base / (unsigned)Cc;          // magic-mul
        int c = (int)(base - a * Cc);              // even, 0..148
        int rv = __ldg(&g_row[a]);
        int row = rv & 0xFFFF;

        const unsigned* rp = &sb[(row << 3) + (c >> 5)];
        unsigned bits = __funnelshift_r(rp[0], rp[1], c);  // low 16 = labels
        float m = (rv >= 0) ? 1.f : 0.f;
        // per lane-pair masks, pairs (2p, 2p+1), p = 0..7
        float mp0 = m, mp1 = m, mp2 = m, mp3 = m;
        float mp4 = m, mp5 = m, mp6 = m, mp7 = m;

        if (c >= 136) {                            // anchor crossing (~9%)
            int n1 = Cc - c;                       // 2..14 lanes in anchor a
            int rv2 = __ldg(&g_row[a + 1]);
            int row2 = rv2 & 0xFFFF;
            unsigned bits2 = sb[row2 << 3];
            bits = (bits & ((1u << n1) - 1u)) | (bits2 << n1);
            float m2 = (rv2 >= 0) ? 1.f : 0.f;
            // pair p entirely in anchor a iff 2p < n1 (n1 even)
            if (n1 <=  2) mp1 = m2;
            if (n1 <=  4) mp2 = m2;
            if (n1 <=  6) mp3 = m2;
            if (n1 <=  8) mp4 = m2;
            if (n1 <= 10) mp5 = m2;
            if (n1 <= 12) mp6 = m2;
            mp7 = m2;
        }

        focal(v0.x, (bits       & 1u) != 0u, mp0, cls0);
        focal(v0.y, ((bits>> 1) & 1u) != 0u, mp0, cls1);
        focal(v0.z, ((bits>> 2) & 1u) != 0u, mp1, cls2);
        focal(v0.w, ((bits>> 3) & 1u) != 0u, mp1, cls3);
        focal(v1.x, ((bits>> 4) & 1u) != 0u, mp2, cls0);
        focal(v1.y, ((bits>> 5) & 1u) != 0u, mp2, cls1);
        focal(v1.z, ((bits>> 6) & 1u) != 0u, mp3, cls2);
        focal(v1.w, ((bits>> 7) & 1u) != 0u, mp3, cls3);
        focal(v2.x, ((bits>> 8) & 1u) != 0u, mp4, cls0);
        focal(v2.y, ((bits>> 9) & 1u) != 0u, mp4, cls1);
        focal(v2.z, ((bits>>10) & 1u) != 0u, mp5, cls2);
        focal(v2.w, ((bits>>11) & 1u) != 0u, mp5, cls3);
        focal(v3.x, ((bits>>12) & 1u) != 0u, mp6, cls0);
        focal(v3.y, ((bits>>13) & 1u) != 0u, mp6, cls1);
        focal(v3.z, ((bits>>14) & 1u) != 0u, mp7, cls2);
        focal(v3.w, ((bits>>15) & 1u) != 0u, mp7, cls3);
    }

    // ---- regression + pos count over 480k anchors ----
    float reg = 0.f, npos = 0.f;
    for (int a1 = tid; a1 < BAc; a1 += stride) {
        int rv = __ldg(&g_row[a1]);
        if (rv & (int)POSBIT) {
            npos += 1.0f;
            float4 p = pred4[a1];
            float4 g = gt4[a1];
            float d[4] = {p.x - g.x, p.y - g.y, p.z - g.z, p.w - g.w};
#pragma unroll
            for (int k = 0; k < 4; k++) {
                float n = fabsf(d[k]);
                reg += (n < (1.0f / 9.0f)) ? 4.5f * n * n : n - (1.0f / 18.0f);
            }
        }
    }

    // ---- block reduction ----
    float cls = (cls0 + cls1) + (cls2 + cls3);
#pragma unroll
    for (int o = 16; o > 0; o >>= 1) {
        cls  += __shfl_down_sync(0xFFFFFFFFu, cls,  o);
        reg  += __shfl_down_sync(0xFFFFFFFFu, reg,  o);
        npos += __shfl_down_sync(0xFFFFFFFFu, npos, o);
    }
    __shared__ float red[3][8];
    int warp = threadIdx.x >> 5, lane = threadIdx.x & 31;
    if (lane == 0) { red[0][warp] = reg; red[1][warp] = cls; red[2][warp] = npos; }
    __syncthreads();

    // ---- commit + last-block finalize (verified ticket pattern) ----
    if (threadIdx.x == 0) {
        float r0 = 0.f, r1 = 0.f, r2 = 0.f;
#pragma unroll
        for (int w = 0; w < 8; w++) { r0 += red[0][w]; r1 += red[1][w]; r2 += red[2][w]; }
        atomicAdd(&g_acc[0], (double)r0);
        atomicAdd(&g_acc[1], (double)r1);
        atomicAdd(&g_acc[2], (double)r2);
        __threadfence();
        unsigned ticket = atomicAdd(&g_done, 1u);
        if (ticket == NBLK - 1) {
            double a0 = __longlong_as_double(
                (long long)atomicExch((unsigned long long*)&g_acc[0], 0ull));
            double a1 = __longlong_as_double(
                (long long)atomicExch((unsigned long long*)&g_acc[1], 0ull));
            double a2 = __longlong_as_double(
                (long long)atomicExch((unsigned long long*)&g_acc[2], 0ull));
            atomicExch(&g_done, 0u);
            double np = (a2 < 1.0) ? 1.0 : a2;
            out[0] = (float)(a0 / (np * 4.0));
            out[1] = (float)(a1 / (np * 6.0));
        }
    }
}

extern "C" void kernel_launch(void* const* d_in, const int* in_sizes, int n_in,
                              void* d_out, int out_size) {
    const float* conf       = (const float*)d_in[0];   // (8, 60000, 150) f32
    const float* pred       = (const float*)d_in[1];   // (8, 60000, 4)   f32
    const float* gt_loc     = (const float*)d_in[2];   // (8, 60000, 4)   f32
    const int*   gt_labels  = (const int*)  d_in[3];   // (8, 20, 5, 5)   i32
    // d_in[4] = counts: not used by the computation
    const int*   labels_bin = (const int*)  d_in[5];   // (8, 60000)      i32
    float* out = (float*)d_out;

    prep_kernel<<<(BAc + 255) / 256, 256>>>(labels_bin, gt_labels);

    main_kernel<<<NBLK, 256>>>((const float4*)conf,
                               (const float4*)pred,
                               (const float4*)gt_loc,
                               out);
}